// round 5
// baseline (speedup 1.0000x reference)
#include <cuda_runtime.h>
#include <cuda_fp16.h>
#include <cstdint>
#include <math.h>

#define B_SZ   1024
#define RANK   256
#define NENT   100000
#define MAXNB  50

// GEMM tiling (fp16 mma.sync m16n8k16, ldmatrix feed)
#define BM 128
#define BN 256
#define BK 32
#define KP 40                        // padded K stride in halves (80B rows)
#define NST 4
#define A_HALVES (BM * KP)           // 5120
#define B_HALVES (BN * KP)           // 10240
#define STG_BYTES ((A_HALVES + B_HALVES) * 2)   // 30720
#define SMEM_BYTES (NST * STG_BYTES)            // 122880

#define QSCALE 524288.0f              // 2^19
#define RSCALE 512.0f                 // 2^9
#define OSCALE 3.725290298461914e-09f // 2^-28

// scratch (allocation-free rule: device globals)
__device__ __align__(16) __half g_q16[B_SZ * RANK];
__device__ __align__(16) __half g_rhs16[(size_t)NENT * RANK];
__device__ __align__(16) float g_Wt[512 * 256];
__device__ __align__(16) float g_W2t[256 * 256];

__device__ __forceinline__ void mma_f16(float* c, const uint32_t* a, uint32_t b0, uint32_t b1) {
    asm volatile(
        "mma.sync.aligned.m16n8k16.row.col.f32.f16.f16.f32 "
        "{%0,%1,%2,%3}, {%4,%5,%6,%7}, {%8,%9}, {%0,%1,%2,%3};\n"
        : "+f"(c[0]), "+f"(c[1]), "+f"(c[2]), "+f"(c[3])
        : "r"(a[0]), "r"(a[1]), "r"(a[2]), "r"(a[3]), "r"(b0), "r"(b1));
}
__device__ __forceinline__ void ldsm_x4(uint32_t* r, uint32_t addr) {
    asm volatile("ldmatrix.sync.aligned.m8n8.x4.shared.b16 {%0,%1,%2,%3}, [%4];"
                 : "=r"(r[0]), "=r"(r[1]), "=r"(r[2]), "=r"(r[3]) : "r"(addr));
}
__device__ __forceinline__ void cp16(uint32_t saddr, const void* gptr, int sz) {
    asm volatile("cp.async.cg.shared.global [%0], [%1], 16, %2;\n"
                 :: "r"(saddr), "l"(gptr), "r"(sz));
}
#define CP_COMMIT() asm volatile("cp.async.commit_group;\n" ::: "memory")
#define CP_WAIT(n)  asm volatile("cp.async.wait_group %0;\n" :: "n"(n) : "memory")

// ---------------------------------------------------------------------------
// Kernel 0: fused transpose (W_w, W2_w) + rhs_w -> fp16 convert
// ---------------------------------------------------------------------------
#define TR_BLOCKS 768
__global__ __launch_bounds__(256) void setup_kernel(const float* __restrict__ W_w,
                                                    const float* __restrict__ W2_w,
                                                    const float* __restrict__ rhs_w) {
    if (blockIdx.x < TR_BLOCKS) {
        int idx = blockIdx.x * 256 + threadIdx.x;
        if (idx < 512 * 256) {
            int i = idx >> 8, j = idx & 255;
            g_Wt[idx] = W_w[j * 512 + i];
        } else {
            int idx2 = idx - 512 * 256;
            if (idx2 < 256 * 256) {
                int k = idx2 >> 8, j = idx2 & 255;
                g_W2t[idx2] = W2_w[j * 256 + k];
            }
        }
        return;
    }
    size_t i8 = ((size_t)(blockIdx.x - TR_BLOCKS) * 256 + threadIdx.x) * 8;
    if (i8 >= (size_t)NENT * RANK) return;
    float4 v0 = *reinterpret_cast<const float4*>(rhs_w + i8);
    float4 v1 = *reinterpret_cast<const float4*>(rhs_w + i8 + 4);
    __half2 h[4];
    h[0] = __floats2half2_rn(v0.x * RSCALE, v0.y * RSCALE);
    h[1] = __floats2half2_rn(v0.z * RSCALE, v0.w * RSCALE);
    h[2] = __floats2half2_rn(v1.x * RSCALE, v1.y * RSCALE);
    h[3] = __floats2half2_rn(v1.z * RSCALE, v1.w * RSCALE);
    *reinterpret_cast<uint4*>(g_rhs16 + i8) = *reinterpret_cast<uint4*>(h);
}

// ---------------------------------------------------------------------------
// Kernel 1: prep — gathers, attention, gating (q -> scaled fp16)
// ---------------------------------------------------------------------------
__global__ __launch_bounds__(256) void prep_kernel(
    const int* __restrict__ x, const int* __restrict__ nb_idx,
    const float* __restrict__ lhs_w, const float* __restrict__ rel_w,
    const float* __restrict__ rhs_w,
    const float* __restrict__ W_b, const float* __restrict__ W2_b,
    const float* __restrict__ Wo_w, const float* __restrict__ Wo_b,
    const float* __restrict__ Uo_w, const float* __restrict__ Uo_b,
    float* __restrict__ aux)
{
    __shared__ float trp[8][512];
    __shared__ float w_sm[8][256];
    __shared__ float alpha[8][64];
    __shared__ float ctx_sm[8][256];
    __shared__ float red[8][8];
    __shared__ float g_sm[8];

    const int t = threadIdx.x;
    const int b0 = blockIdx.x * 8;
    const int lane = t & 31;
    const int warp = t >> 5;

    float lhsrel[8];
#pragma unroll
    for (int bb = 0; bb < 8; bb++) {
        int b = b0 + bb;
        int i0 = x[b * 3 + 0];
        int i1 = x[b * 3 + 1];
        int i2 = x[b * 3 + 2];
        float lv = lhs_w[(size_t)i0 * RANK + t];
        float rv = rel_w[(size_t)i1 * RANK + t];
        float hv = rhs_w[(size_t)i2 * RANK + t];
        trp[bb][t]       = lv;
        trp[bb][256 + t] = rv;
        lhsrel[bb] = lv * rv;
        if (aux) {
            aux[(size_t)b * RANK + t]              = lv;
            aux[262144 + (size_t)b * RANK + t]     = rv;
            aux[2 * 262144 + (size_t)b * RANK + t] = hv;
        }
    }
    __syncthreads();

    {
        float acc[8];
#pragma unroll
        for (int bb = 0; bb < 8; bb++) acc[bb] = 0.f;
        for (int i = 0; i < 512; i += 4) {
            float wv0 = g_Wt[(i + 0) * 256 + t];
            float wv1 = g_Wt[(i + 1) * 256 + t];
            float wv2 = g_Wt[(i + 2) * 256 + t];
            float wv3 = g_Wt[(i + 3) * 256 + t];
#pragma unroll
            for (int bb = 0; bb < 8; bb++) {
                const float4 tv = *reinterpret_cast<const float4*>(&trp[bb][i]);
                acc[bb] += wv0 * tv.x + wv1 * tv.y + wv2 * tv.z + wv3 * tv.w;
            }
        }
        float bias = W_b[t];
#pragma unroll
        for (int bb = 0; bb < 8; bb++) w_sm[bb][t] = acc[bb] + bias;
    }
    __syncthreads();

    {
        int bb = warp;
        int b = b0 + bb;
        for (int m = 0; m < MAXNB; m++) {
            int nb = __ldg(&nb_idx[b * MAXNB + m]);
            const float* r = rhs_w + (size_t)nb * RANK;
            float s = 0.f;
#pragma unroll
            for (int j = 0; j < 8; j++) {
                int k = lane + 32 * j;
                s += w_sm[bb][k] * __ldg(&r[k]);
            }
#pragma unroll
            for (int o = 16; o > 0; o >>= 1) s += __shfl_xor_sync(0xffffffffu, s, o);
            if (lane == 0) alpha[bb][m] = s;
        }
        __syncwarp();
        float v1 = (lane < MAXNB) ? alpha[bb][lane] : -1e30f;
        float v2 = (lane + 32 < MAXNB) ? alpha[bb][lane + 32] : -1e30f;
        float mx = fmaxf(v1, v2);
#pragma unroll
        for (int o = 16; o > 0; o >>= 1) mx = fmaxf(mx, __shfl_xor_sync(0xffffffffu, mx, o));
        float e1 = (lane < MAXNB) ? expf(v1 - mx) : 0.f;
        float e2 = (lane + 32 < MAXNB) ? expf(v2 - mx) : 0.f;
        float sm = e1 + e2;
#pragma unroll
        for (int o = 16; o > 0; o >>= 1) sm += __shfl_xor_sync(0xffffffffu, sm, o);
        float inv = 1.f / sm;
        if (lane < MAXNB) alpha[bb][lane] = e1 * inv;
        if (lane + 32 < MAXNB) alpha[bb][lane + 32] = e2 * inv;
    }
    __syncthreads();

#pragma unroll
    for (int bb = 0; bb < 8; bb++) {
        int base = (b0 + bb) * MAXNB;
        float acc = 0.f;
        for (int m = 0; m < MAXNB; m++) {
            int nb = __ldg(&nb_idx[base + m]);
            acc += alpha[bb][m] * __ldg(&rhs_w[(size_t)nb * RANK + t]);
        }
        ctx_sm[bb][t] = acc;
    }
    __syncthreads();

    float ec[8];
    {
        float acc[8];
#pragma unroll
        for (int bb = 0; bb < 8; bb++) acc[bb] = 0.f;
        for (int k = 0; k < 256; k += 4) {
            float w0 = g_W2t[(k + 0) * 256 + t];
            float w1 = g_W2t[(k + 1) * 256 + t];
            float w2 = g_W2t[(k + 2) * 256 + t];
            float w3 = g_W2t[(k + 3) * 256 + t];
#pragma unroll
            for (int bb = 0; bb < 8; bb++) {
                const float4 cv = *reinterpret_cast<const float4*>(&ctx_sm[bb][k]);
                acc[bb] += w0 * cv.x + w1 * cv.y + w2 * cv.z + w3 * cv.w;
            }
        }
        float bias = W2_b[t];
#pragma unroll
        for (int bb = 0; bb < 8; bb++) {
            ec[bb] = acc[bb] + bias;
            if (aux) aux[3 * 262144 + (size_t)(b0 + bb) * RANK + t] = ec[bb];
        }
    }

    {
        float uo = Uo_w[t], wo = Wo_w[t];
#pragma unroll
        for (int bb = 0; bb < 8; bb++) {
            float c = uo * lhsrel[bb] + wo * ec[bb];
#pragma unroll
            for (int o = 16; o > 0; o >>= 1) c += __shfl_xor_sync(0xffffffffu, c, o);
            if (lane == 0) red[bb][warp] = c;
        }
        __syncthreads();
        if (t < 8) {
            float s = 0.f;
#pragma unroll
            for (int w = 0; w < 8; w++) s += red[t][w];
            s += Uo_b[0] + Wo_b[0];
            g_sm[t] = 1.f / (1.f + expf(-s));
        }
        __syncthreads();
    }

#pragma unroll
    for (int bb = 0; bb < 8; bb++) {
        float g = g_sm[bb];
        float q = lhsrel[bb] * (g * ec[bb] + 1.f - g);
        g_q16[(size_t)(b0 + bb) * RANK + t] = __float2half_rn(q * QSCALE);
    }
}

// ---------------------------------------------------------------------------
// Kernel 2: fp16 GEMM, 512 threads, 16 warps (2m x 8n), warp tile 64x32.
// ldmatrix.x4 fragment feed (bank-conflict-free with KP=40), 4-stage cp.async.
// ---------------------------------------------------------------------------
__global__ __launch_bounds__(512, 1) void gemm_f16_kernel(float* __restrict__ out)
{
    extern __shared__ __half smem[];

    const int tid = threadIdx.x;
    const int m0 = blockIdx.x * BM;
    const int n0 = blockIdx.y * BN;
    const int lane = tid & 31;
    const int warp = tid >> 5;
    const int wm = warp & 1;     // m offset 64*wm
    const int wn = warp >> 1;    // n offset 32*wn
    const int gid = lane >> 2;
    const int qid = lane & 3;

    const uint32_t smem_u32 = (uint32_t)__cvta_generic_to_shared(smem);
    // ldmatrix source addresses (lane-dependent): row (lane&15), col half (lane>>4)*8
    const int lrow = lane & 15;
    const int lcol16 = (lane >> 4) * 16;    // byte offset within k16 block

    auto issue_stage = [&](int buf, int kc) {
        uint32_t base = smem_u32 + (uint32_t)buf * STG_BYTES;
        {                                   // A: 128 rows x 32 halves, 1 cp/thread
            int row = tid >> 2, kq = tid & 3;
            cp16(base + (uint32_t)(row * (KP * 2) + kq * 16),
                 g_q16 + (size_t)(m0 + row) * RANK + kc + kq * 8, 16);
        }
        uint32_t bbase = base + (uint32_t)(A_HALVES * 2);
#pragma unroll
        for (int i = 0; i < 2; i++) {       // B: 256 rows x 32 halves, 2 cp/thread
            int idx = tid + i * 512;
            int row = idx >> 2, kq = idx & 3;
            int nr = n0 + row;
            int ok = nr < NENT;
            cp16(bbase + (uint32_t)(row * (KP * 2) + kq * 16),
                 g_rhs16 + (size_t)(ok ? nr : 0) * RANK + kc + kq * 8, ok ? 16 : 0);
        }
    };

    float acc[4][4][4];
#pragma unroll
    for (int i = 0; i < 4; i++)
#pragma unroll
        for (int f = 0; f < 4; f++)
#pragma unroll
            for (int r = 0; r < 4; r++) acc[i][f][r] = 0.f;

    issue_stage(0, 0);      CP_COMMIT();
    issue_stage(1, BK);     CP_COMMIT();
    issue_stage(2, 2 * BK); CP_COMMIT();

#pragma unroll 1
    for (int c = 0; c < RANK / BK; c++) {
        CP_WAIT(2);
        __syncthreads();

        if (c + 3 < RANK / BK) issue_stage((c + 3) & (NST - 1), (c + 3) * BK);
        CP_COMMIT();

        const uint32_t abase = smem_u32 + (uint32_t)(c & (NST - 1)) * STG_BYTES;
        const uint32_t bbase = abase + (uint32_t)(A_HALVES * 2);

#pragma unroll
        for (int kk = 0; kk < 2; kk++) {                 // two k16 steps
            uint32_t a[4][4];
#pragma unroll
            for (int i = 0; i < 4; i++)
                ldsm_x4(a[i], abase + (uint32_t)((wm * 64 + i * 16 + lrow) * (KP * 2)
                                                 + kk * 32 + lcol16));
            uint32_t b[2][4];
#pragma unroll
            for (int j = 0; j < 2; j++)
                ldsm_x4(b[j], bbase + (uint32_t)((wn * 32 + j * 16 + lrow) * (KP * 2)
                                                 + kk * 32 + lcol16));
#pragma unroll
            for (int i = 0; i < 4; i++)
#pragma unroll
                for (int f = 0; f < 4; f++) {
                    int j = f >> 1, h = f & 1;
                    mma_f16(acc[i][f], a[i], b[j][h], b[j][h + 2]);
                }
        }
    }

    // epilogue: descale + streaming stores
#pragma unroll
    for (int i = 0; i < 4; i++) {
        int r = m0 + wm * 64 + i * 16 + gid;
#pragma unroll
        for (int f = 0; f < 4; f++) {
            int cb = n0 + wn * 32 + f * 8 + 2 * qid;
            if (cb < NENT) {
                __stcs(reinterpret_cast<float2*>(out + (size_t)r * NENT + cb),
                       make_float2(acc[i][f][0] * OSCALE, acc[i][f][1] * OSCALE));
                __stcs(reinterpret_cast<float2*>(out + (size_t)(r + 8) * NENT + cb),
                       make_float2(acc[i][f][2] * OSCALE, acc[i][f][3] * OSCALE));
            }
        }
    }
}

// ---------------------------------------------------------------------------
extern "C" void kernel_launch(void* const* d_in, const int* in_sizes, int n_in,
                              void* d_out, int out_size) {
    const int*   x      = (const int*)d_in[0];
    const int*   nb     = (const int*)d_in[1];
    const float* lhs_w  = (const float*)d_in[2];
    const float* rel_w  = (const float*)d_in[3];
    const float* rhs_w  = (const float*)d_in[4];
    const float* W_w    = (const float*)d_in[5];
    const float* W_b    = (const float*)d_in[6];
    const float* W2_w   = (const float*)d_in[7];
    const float* W2_b   = (const float*)d_in[8];
    const float* Wo_w   = (const float*)d_in[9];
    const float* Wo_b   = (const float*)d_in[10];
    const float* Uo_w   = (const float*)d_in[11];
    const float* Uo_b   = (const float*)d_in[12];
    float* out = (float*)d_out;

    float* aux = nullptr;
    if (out_size >= 102400000 + 4 * 262144) aux = out + 102400000;

    static bool attr_set = false;
    if (!attr_set) {
        cudaFuncSetAttribute(gemm_f16_kernel,
                             cudaFuncAttributeMaxDynamicSharedMemorySize, SMEM_BYTES);
        attr_set = true;
    }

    int conv_blocks = (NENT * RANK / 8 + 255) / 256;
    setup_kernel<<<TR_BLOCKS + conv_blocks, 256>>>(W_w, W2_w, rhs_w);
    prep_kernel<<<B_SZ / 8, 256>>>(x, nb, lhs_w, rel_w, rhs_w,
                                   W_b, W2_b, Wo_w, Wo_b, Uo_w, Uo_b, aux);
    dim3 grid(B_SZ / BM, (NENT + BN - 1) / BN);
    gemm_f16_kernel<<<grid, 512, SMEM_BYTES>>>(out);
}